// round 16
// baseline (speedup 1.0000x reference)
#include <cuda_runtime.h>

#define NN 8192
#define VV 8
#define OO 16
#define HH 128
#define ROW (4*VV + 3*OO)   // 80 floats per input row
#define TPB 128
#define WPB 4               // warps per block = 2 pairs
#define PAIRS 2             // warp-pairs per block; pair handles NPW rows
#define NPW 4               // problem rows (n) per pair: lane = ng*8 + v
#define NPART (NN / (PAIRS * NPW))   // 1024 blocks
#define BUFCAP 256          // power-of-2 ring (max pending 31+128=159)
#define OPAD 17             // obstacle array pad: conflict-free

// Per-block partials (plain stores; no zeroing kernel)
__device__ float g_pd[NPART];
__device__ float g_po[NPART];
__device__ float g_pv[NPART];
__device__ int   g_oc[NPART];
__device__ int   g_vc[NPART];
__device__ unsigned int g_done;   // zero-init; last block resets each launch

__inline__ __device__ float warp_red_f(float v) {
    #pragma unroll
    for (int o = 16; o > 0; o >>= 1) v += __shfl_down_sync(0xffffffffu, v, o);
    return v;
}
__inline__ __device__ int warp_red_i(int v) {
    #pragma unroll
    for (int o = 16; o > 0; o >>= 1) v += __shfl_down_sync(0xffffffffu, v, o);
    return v;
}

__inline__ __device__ float fast_sqrt(float x) {
    float r;
    asm("sqrt.approx.f32 %0, %1;" : "=f"(r) : "f"(x));
    return r;
}

// Warp-pair half-split: warps come in pairs sharing the same 4 problem rows.
// Warp hf=0 walks steps 0..63, warp hf=1 walks steps 64..127. Each warp's
// INTERNAL layout is identical to the proven R13 kernel (lane = ng*8 + v,
// ring compaction, group-tagged drain). The only cross-warp machinery is the
// half-1 start offset: pass-1 partials (hf=0: steps 0..31, hf=1: 32..63)
// exchanged through smem with one __syncthreads.
// 2x warps (4096) at -25% per-thread critical path vs R13 -> attacks the
// proven binder (latency exposure at occ=20%).
__global__ void __launch_bounds__(TPB) loss_kernel(
    const float* __restrict__ pred,     // (N, V, H) f32
    const float* __restrict__ inputs,   // (N, 80) f32
    float* __restrict__ out)
{
    const int warp = threadIdx.x >> 5;
    const int lane = threadIdx.x & 31;
    const int pair = warp >> 1;          // warp-pair (0..1)
    const int hf   = warp & 1;           // h-half (0: steps 0-63, 1: 64-127)
    const int ng   = lane >> 3;          // n-group within pair (0..3)
    const int v    = lane & 7;           // vehicle
    const int n    = (blockIdx.x * PAIRS + pair) * NPW + ng;

    const float* row = inputs + (size_t)n * ROW;

    __shared__ float s_ox[PAIRS][NPW][OPAD];
    __shared__ float s_oy[PAIRS][NPW][OPAD];
    __shared__ float s_r2[PAIRS][NPW][OPAD];
    __shared__ float2 s_buf[WPB][BUFCAP];
    __shared__ unsigned char s_grp[WPB][BUFCAP];
    __shared__ float s_mx[PAIRS][NPW][VV], s_my[PAIRS][NPW][VV];

    // ---- obstacles -> smem (each warp writes its pair's 64 slots; the two
    // warps of a pair write identical values - benign) ----
    #pragma unroll
    for (int idx = lane; idx < NPW * OO; idx += 32) {
        int g = idx >> 4, o = idx & 15;
        const float* orow = inputs
            + (size_t)((blockIdx.x * PAIRS + pair) * NPW + g) * ROW + 4 * VV + 3 * o;
        float cx = orow[0], cy = orow[1];
        float r  = orow[2] + 1.0f;               // + OBST_RADIUS
        s_ox[pair][g][o] = cx;
        s_oy[pair][g][o] = cy;
        s_r2[pair][g][o] = (r > 0.0f) ? r * r : -1.0f;
    }
    __syncwarp();

    // ---- per-lane prune box for its own n-group (broadcast LDS reads) ----
    float mnx = 1e30f, mxx = -1e30f, mny = 1e30f, mxy = -1e30f, rmx = -1e30f;
    #pragma unroll
    for (int o = 0; o < OO; ++o) {
        float cx = s_ox[pair][ng][o];
        float cy = s_oy[pair][ng][o];
        float r2 = s_r2[pair][ng][o];
        mnx = fminf(mnx, cx); mxx = fmaxf(mxx, cx);
        mny = fminf(mny, cy); mxy = fmaxf(mxy, cy);
        rmx = fmaxf(rmx, r2);
    }
    rmx = (rmx > 0.0f) ? fast_sqrt(rmx) : 0.0f;   // max effective radius
    const float cbx = 0.5f * (mnx + mxx), hbx = 0.5f * (mxx - mnx) + rmx;
    const float cby = 0.5f * (mny + mxy), hby = 0.5f * (mxy - mny) + rmx;

    // ---- vehicle start / target ----
    const float4 vd = *(const float4*)(row + 4 * v);
    const float x0 = vd.x, y0 = vd.y;
    const float tx = vd.z, ty = vd.w;

    const float4* p4 = (const float4*)(pred + (size_t)(n * VV + v) * HH);

    // ---- pass 1: 32-step partial sums; hf=0 publishes steps 0..31 ----
    float sx = 0.0f, sy = 0.0f;
    {
        const float4* pp = p4 + hf * 8;   // hf=0: idx 0..7; hf=1: idx 8..15
        #pragma unroll
        for (int i = 0; i < 8; ++i) {
            float4 p = pp[i];
            float s, c;
            __sincosf(p.x, &s, &c); sx += c; sy += s;
            __sincosf(p.y, &s, &c); sx += c; sy += s;
            __sincosf(p.z, &s, &c); sx += c; sy += s;
            __sincosf(p.w, &s, &c); sx += c; sy += s;
        }
    }
    if (hf == 0) { s_mx[pair][ng][v] = sx; s_my[pair][ng][v] = sy; }
    __syncthreads();
    float x, y;
    if (hf) {
        x = fmaf(2.0f, s_mx[pair][ng][v] + sx, x0);  // STEP=2 * cum(0..63)
        y = fmaf(2.0f, s_my[pair][ng][v] + sy, y0);
    } else {
        x = x0; y = y0;
    }

    // ---- walk 64 steps: 16 batches of 4; loads pipelined dist 2 ----
    float dist_sum = 0.0f, oinv = 0.0f, vinv = 0.0f;
    int ocnt = 0, vcnt = 0;
    int head = 0, pending = 0;              // warp-uniform ring state
    const unsigned lt_mask = (1u << lane) - 1u;
    const bool vact = (v < 7);

    const float4* pw = p4 + hf * 16;        // walk range (idx 0..15 / 16..31)
    float4 pa = pw[0];
    float4 pb = pw[1];

    #pragma unroll 1
    for (int i = 0; i < 16; ++i) {
        float4 pc = pw[(i + 2 < 16) ? i + 2 : i];
        float4 p = pa;
        pa = pb; pb = pc;

        // serial position chain: only the fmaf is dependent (lat 4)
        float xs[4], ys[4];
        {
            float s, c;
            __sincosf(p.x, &s, &c);
            x = fmaf(2.0f, c, x); y = fmaf(2.0f, s, y); xs[0] = x; ys[0] = y;
            __sincosf(p.y, &s, &c);
            x = fmaf(2.0f, c, x); y = fmaf(2.0f, s, y); xs[1] = x; ys[1] = y;
            __sincosf(p.z, &s, &c);
            x = fmaf(2.0f, c, x); y = fmaf(2.0f, s, y); xs[2] = x; ys[2] = y;
            __sincosf(p.w, &s, &c);
            x = fmaf(2.0f, c, x); y = fmaf(2.0f, s, y); xs[3] = x; ys[3] = y;
        }

        // batched target-distance terms
        #pragma unroll
        for (int j = 0; j < 4; ++j) {
            float dx = tx - xs[j], dy = ty - ys[j];
            dist_sum += fast_sqrt(fmaf(dx, dx, dy * dy));
        }

        // batched in-box tests (per-lane box) + ballots
        bool ib[4];
        unsigned m[4];
        #pragma unroll
        for (int j = 0; j < 4; ++j)
            ib[j] = (fabsf(xs[j] - cbx) <= hbx) & (fabsf(ys[j] - cby) <= hby);
        #pragma unroll
        for (int j = 0; j < 4; ++j)
            m[j] = __ballot_sync(0xffffffffu, ib[j]);

        // compact appends (tagged with n-group)
        #pragma unroll
        for (int j = 0; j < 4; ++j) {
            if (ib[j]) {
                int slot = (head + pending + __popc(m[j] & lt_mask)) & (BUFCAP-1);
                s_buf[warp][slot] = make_float2(xs[j], ys[j]);
                s_grp[warp][slot] = (unsigned char)ng;
            }
            pending += __popc(m[j]);
        }

        // batched vehicle shfls (neighbor v+1 = lane+1), then terms
        float xn[4], yn[4];
        #pragma unroll
        for (int j = 0; j < 4; ++j) {
            xn[j] = __shfl_down_sync(0xffffffffu, xs[j], 1);
            yn[j] = __shfl_down_sync(0xffffffffu, ys[j], 1);
        }
        if (vact) {
            #pragma unroll
            for (int j = 0; j < 4; ++j) {
                float bxv = xn[j] - xs[j], byv = yn[j] - ys[j];
                float d2 = fmaf(bxv, bxv, byv * byv);
                if (d2 < 1.0f) { vinv += rsqrtf(d2); vcnt++; }   // VEH_R^2 = 1
            }
        }

        // drain (warp-uniform): 32 tagged points per pass
        while (pending >= 32) {
            __syncwarp();
            int slot = (head + lane) & (BUFCAP-1);
            float2 q = s_buf[warp][slot];
            int g = s_grp[warp][slot];
            #pragma unroll
            for (int o = 0; o < OO; ++o) {
                float ax = q.x - s_ox[pair][g][o];
                float ay = q.y - s_oy[pair][g][o];
                float d2o = fmaf(ax, ax, ay * ay);
                if (d2o < s_r2[pair][g][o]) { oinv += rsqrtf(d2o); ocnt++; }
            }
            head = (head + 32) & (BUFCAP-1);
            pending -= 32;
        }
    }

    // final flush
    if (pending > 0) {
        __syncwarp();
        if (lane < pending) {
            int slot = (head + lane) & (BUFCAP-1);
            float2 q = s_buf[warp][slot];
            int g = s_grp[warp][slot];
            #pragma unroll
            for (int o = 0; o < OO; ++o) {
                float ax = q.x - s_ox[pair][g][o];
                float ay = q.y - s_oy[pair][g][o];
                float d2o = fmaf(ax, ax, ay * ay);
                if (d2o < s_r2[pair][g][o]) { oinv += rsqrtf(d2o); ocnt++; }
            }
        }
    }

    // ---- warp -> block reduction ----
    dist_sum = warp_red_f(dist_sum);
    oinv     = warp_red_f(oinv);
    vinv     = warp_red_f(vinv);
    ocnt     = warp_red_i(ocnt);
    vcnt     = warp_red_i(vcnt);

    __shared__ float sd[WPB], so[WPB], sv[WPB];
    __shared__ int soc[WPB], svc[WPB];
    if (lane == 0) {
        sd[warp] = dist_sum; so[warp] = oinv; sv[warp] = vinv;
        soc[warp] = ocnt; svc[warp] = vcnt;
    }
    __syncthreads();
    if (warp == 0) {
        float d = (lane < WPB) ? sd[lane] : 0.0f;
        float a = (lane < WPB) ? so[lane] : 0.0f;
        float b = (lane < WPB) ? sv[lane] : 0.0f;
        int   c = (lane < WPB) ? soc[lane] : 0;
        int   e = (lane < WPB) ? svc[lane] : 0;
        d = warp_red_f(d); a = warp_red_f(a); b = warp_red_f(b);
        c = warp_red_i(c); e = warp_red_i(e);
        if (lane == 0) {
            g_pd[blockIdx.x] = d;
            g_po[blockIdx.x] = a;
            g_pv[blockIdx.x] = b;
            g_oc[blockIdx.x] = c;
            g_vc[blockIdx.x] = e;
        }
    }

    // ---- last-block finalize ----
    __shared__ bool isLast;
    __threadfence();
    if (threadIdx.x == 0) {
        unsigned int prev = atomicAdd(&g_done, 1u);
        isLast = (prev == NPART - 1);
    }
    __syncthreads();
    if (!isLast) return;

    float d = 0.0f, a = 0.0f, b = 0.0f;
    int c = 0, e = 0;
    #pragma unroll
    for (int i = 0; i < NPART / TPB; ++i) {
        int idx = threadIdx.x + i * TPB;
        d += g_pd[idx]; a += g_po[idx]; b += g_pv[idx];
        c += g_oc[idx]; e += g_vc[idx];
    }
    d = warp_red_f(d); a = warp_red_f(a); b = warp_red_f(b);
    c = warp_red_i(c); e = warp_red_i(e);
    if (lane == 0) {
        sd[warp] = d; so[warp] = a; sv[warp] = b; soc[warp] = c; svc[warp] = e;
    }
    __syncthreads();
    if (warp == 0) {
        d = (lane < WPB) ? sd[lane] : 0.0f;
        a = (lane < WPB) ? so[lane] : 0.0f;
        b = (lane < WPB) ? sv[lane] : 0.0f;
        c = (lane < WPB) ? soc[lane] : 0;
        e = (lane < WPB) ? svc[lane] : 0;
        d = warp_red_f(d); a = warp_red_f(a); b = warp_red_f(b);
        c = warp_red_i(c); e = warp_red_i(e);
        if (lane == 0) {
            double loss = (double)d / ((double)NN * VV * HH);   // DIST_COST=1
            if (c > 0) loss += ((double)a / (double)c) * 0.1;   // OBST_COST
            if (e > 0) loss += ((double)b / (double)e) * 0.1;   // VEH_COST
            out[0] = (float)loss;
            g_done = 0;   // reset for next graph replay
        }
    }
}

extern "C" void kernel_launch(void* const* d_in, const int* in_sizes, int n_in,
                              void* d_out, int out_size) {
    const float* pred   = (const float*)d_in[0];   // (N, V, H, 1) f32
    const float* inputs = (const float*)d_in[1];   // (N, 80) f32
    float* out = (float*)d_out;

    loss_kernel<<<NPART, TPB>>>(pred, inputs, out);
}

// round 17
// speedup vs baseline: 1.1282x; 1.1282x over previous
#include <cuda_runtime.h>

#define NN 8192
#define VV 8
#define OO 16
#define HH 128
#define ROW (4*VV + 3*OO)   // 80 floats per input row
#define TPB 128
#define WPB 4               // warps per block
#define NPW 4               // problem rows (n) per warp: lane = ng*8 + v
#define NPART (NN / (WPB * NPW))   // 512 blocks
#define BUFCAP 256          // power-of-2 ring (max pending 31+128=159)
#define OPAD 17             // obstacle array pad: conflict-free

// Per-block partials (plain stores; no zeroing kernel)
__device__ float g_pd[NPART];
__device__ float g_po[NPART];
__device__ float g_pv[NPART];
__device__ int   g_oc[NPART];
__device__ int   g_vc[NPART];
__device__ unsigned int g_done;   // zero-init; last block resets each launch

__inline__ __device__ float warp_red_f(float v) {
    #pragma unroll
    for (int o = 16; o > 0; o >>= 1) v += __shfl_down_sync(0xffffffffu, v, o);
    return v;
}
__inline__ __device__ int warp_red_i(int v) {
    #pragma unroll
    for (int o = 16; o > 0; o >>= 1) v += __shfl_down_sync(0xffffffffu, v, o);
    return v;
}

__inline__ __device__ float fast_sqrt(float x) {
    float r;
    asm("sqrt.approx.f32 %0, %1;" : "=f"(r) : "f"(x));
    return r;
}

// R13 base (best: 30.5us) + two deltas:
//  1. any-hit gate: one combined ballot skips the whole ballot/append/drain
//     block when no lane of the warp is in-box this 4-step batch (the common
//     case late in the trajectory). Obstacle-sum order is set-semantic, so
//     reordering appends is exact.
//  2. prefetch depth 3 (was 2) on the prediction loads.
__global__ void __launch_bounds__(TPB) loss_kernel(
    const float* __restrict__ pred,     // (N, V, H) f32
    const float* __restrict__ inputs,   // (N, 80) f32
    float* __restrict__ out)
{
    const int warp = threadIdx.x >> 5;
    const int lane = threadIdx.x & 31;
    const int ng   = lane >> 3;          // n-group within warp (0..3)
    const int v    = lane & 7;           // vehicle
    const int n    = (blockIdx.x * WPB + warp) * NPW + ng;

    const float* row = inputs + (size_t)n * ROW;

    __shared__ float s_ox[WPB][NPW][OPAD];
    __shared__ float s_oy[WPB][NPW][OPAD];
    __shared__ float s_r2[WPB][NPW][OPAD];
    __shared__ float2 s_buf[WPB][BUFCAP];
    __shared__ unsigned char s_grp[WPB][BUFCAP];

    // ---- obstacles -> smem (64 obstacle slots, 2 per lane) ----
    #pragma unroll
    for (int idx = lane; idx < NPW * OO; idx += 32) {
        int g = idx >> 4, o = idx & 15;
        const float* orow = inputs + (size_t)((blockIdx.x * WPB + warp) * NPW + g) * ROW
                            + 4 * VV + 3 * o;
        float cx = orow[0], cy = orow[1];
        float r  = orow[2] + 1.0f;               // + OBST_RADIUS
        s_ox[warp][g][o] = cx;
        s_oy[warp][g][o] = cy;
        s_r2[warp][g][o] = (r > 0.0f) ? r * r : -1.0f;
    }
    __syncwarp();

    // ---- per-lane prune box for its own n-group (broadcast LDS reads) ----
    float mnx = 1e30f, mxx = -1e30f, mny = 1e30f, mxy = -1e30f, rmx = -1e30f;
    #pragma unroll
    for (int o = 0; o < OO; ++o) {
        float cx = s_ox[warp][ng][o];
        float cy = s_oy[warp][ng][o];
        float r2 = s_r2[warp][ng][o];
        mnx = fminf(mnx, cx); mxx = fmaxf(mxx, cx);
        mny = fminf(mny, cy); mxy = fmaxf(mxy, cy);
        rmx = fmaxf(rmx, r2);
    }
    rmx = (rmx > 0.0f) ? fast_sqrt(rmx) : 0.0f;   // max effective radius
    const float cbx = 0.5f * (mnx + mxx), hbx = 0.5f * (mxx - mnx) + rmx;
    const float cby = 0.5f * (mny + mxy), hby = 0.5f * (mxy - mny) + rmx;

    // ---- vehicle start / target (vectorized: 16B-aligned) ----
    const float4 vd = *(const float4*)(row + 4 * v);
    float x = vd.x, y = vd.y;
    const float tx = vd.z, ty = vd.w;

    const float4* p4 = (const float4*)(pred + (size_t)(n * VV + v) * HH);

    // ---- single pass: 32 batches of 4 steps; loads pipelined dist 3 ----
    float dist_sum = 0.0f, oinv = 0.0f, vinv = 0.0f;
    int ocnt = 0, vcnt = 0;
    int head = 0, pending = 0;              // warp-uniform ring state
    const unsigned lt_mask = (1u << lane) - 1u;
    const bool vact = (v < 7);

    float4 pa = __ldcs(&p4[0]);
    float4 pb = __ldcs(&p4[1]);
    float4 pc = __ldcs(&p4[2]);

    #pragma unroll 1
    for (int i = 0; i < HH / 4; ++i) {
        // issue the i+3 load before any compute on pa
        float4 pd_ = __ldcs(&p4[(i + 3 < HH / 4) ? i + 3 : i]);
        float4 p = pa;
        pa = pb; pb = pc; pc = pd_;

        // serial position chain: only the fmaf is dependent (lat 4)
        float xs[4], ys[4];
        {
            float s, c;
            __sincosf(p.x, &s, &c);
            x = fmaf(2.0f, c, x); y = fmaf(2.0f, s, y); xs[0] = x; ys[0] = y;
            __sincosf(p.y, &s, &c);
            x = fmaf(2.0f, c, x); y = fmaf(2.0f, s, y); xs[1] = x; ys[1] = y;
            __sincosf(p.z, &s, &c);
            x = fmaf(2.0f, c, x); y = fmaf(2.0f, s, y); xs[2] = x; ys[2] = y;
            __sincosf(p.w, &s, &c);
            x = fmaf(2.0f, c, x); y = fmaf(2.0f, s, y); xs[3] = x; ys[3] = y;
        }

        // batched target-distance terms
        #pragma unroll
        for (int j = 0; j < 4; ++j) {
            float dx = tx - xs[j], dy = ty - ys[j];
            dist_sum += fast_sqrt(fmaf(dx, dx, dy * dy));
        }

        // batched in-box tests (per-lane box)
        bool ib[4];
        #pragma unroll
        for (int j = 0; j < 4; ++j)
            ib[j] = (fabsf(xs[j] - cbx) <= hbx) & (fabsf(ys[j] - cby) <= hby);

        // any-hit gate: skip the whole append/drain block when no lane hit
        unsigned anyhit = __ballot_sync(0xffffffffu, ib[0] | ib[1] | ib[2] | ib[3]);
        if (anyhit) {
            unsigned m[4];
            #pragma unroll
            for (int j = 0; j < 4; ++j)
                m[j] = __ballot_sync(0xffffffffu, ib[j]);

            #pragma unroll
            for (int j = 0; j < 4; ++j) {
                if (ib[j]) {
                    int slot = (head + pending + __popc(m[j] & lt_mask)) & (BUFCAP-1);
                    s_buf[warp][slot] = make_float2(xs[j], ys[j]);
                    s_grp[warp][slot] = (unsigned char)ng;
                }
                pending += __popc(m[j]);
            }

            // drain (warp-uniform): 32 tagged points per pass
            while (pending >= 32) {
                __syncwarp();
                int slot = (head + lane) & (BUFCAP-1);
                float2 q = s_buf[warp][slot];
                int g = s_grp[warp][slot];
                #pragma unroll
                for (int o = 0; o < OO; ++o) {
                    float ax = q.x - s_ox[warp][g][o];
                    float ay = q.y - s_oy[warp][g][o];
                    float d2o = fmaf(ax, ax, ay * ay);
                    if (d2o < s_r2[warp][g][o]) { oinv += rsqrtf(d2o); ocnt++; }
                }
                head = (head + 32) & (BUFCAP-1);
                pending -= 32;
            }
        }

        // batched vehicle shfls (neighbor v+1 = lane+1), then terms
        float xn[4], yn[4];
        #pragma unroll
        for (int j = 0; j < 4; ++j) {
            xn[j] = __shfl_down_sync(0xffffffffu, xs[j], 1);
            yn[j] = __shfl_down_sync(0xffffffffu, ys[j], 1);
        }
        if (vact) {
            #pragma unroll
            for (int j = 0; j < 4; ++j) {
                float bxv = xn[j] - xs[j], byv = yn[j] - ys[j];
                float d2 = fmaf(bxv, bxv, byv * byv);
                if (d2 < 1.0f) { vinv += rsqrtf(d2); vcnt++; }   // VEH_R^2 = 1
            }
        }
    }

    // final flush
    if (pending > 0) {
        __syncwarp();
        if (lane < pending) {
            int slot = (head + lane) & (BUFCAP-1);
            float2 q = s_buf[warp][slot];
            int g = s_grp[warp][slot];
            #pragma unroll
            for (int o = 0; o < OO; ++o) {
                float ax = q.x - s_ox[warp][g][o];
                float ay = q.y - s_oy[warp][g][o];
                float d2o = fmaf(ax, ax, ay * ay);
                if (d2o < s_r2[warp][g][o]) { oinv += rsqrtf(d2o); ocnt++; }
            }
        }
    }

    // ---- warp -> block reduction ----
    dist_sum = warp_red_f(dist_sum);
    oinv     = warp_red_f(oinv);
    vinv     = warp_red_f(vinv);
    ocnt     = warp_red_i(ocnt);
    vcnt     = warp_red_i(vcnt);

    __shared__ float sd[WPB], so[WPB], sv[WPB];
    __shared__ int soc[WPB], svc[WPB];
    if (lane == 0) {
        sd[warp] = dist_sum; so[warp] = oinv; sv[warp] = vinv;
        soc[warp] = ocnt; svc[warp] = vcnt;
    }
    __syncthreads();
    if (warp == 0) {
        float d = (lane < WPB) ? sd[lane] : 0.0f;
        float a = (lane < WPB) ? so[lane] : 0.0f;
        float b = (lane < WPB) ? sv[lane] : 0.0f;
        int   c = (lane < WPB) ? soc[lane] : 0;
        int   e = (lane < WPB) ? svc[lane] : 0;
        d = warp_red_f(d); a = warp_red_f(a); b = warp_red_f(b);
        c = warp_red_i(c); e = warp_red_i(e);
        if (lane == 0) {
            g_pd[blockIdx.x] = d;
            g_po[blockIdx.x] = a;
            g_pv[blockIdx.x] = b;
            g_oc[blockIdx.x] = c;
            g_vc[blockIdx.x] = e;
        }
    }

    // ---- last-block finalize ----
    __shared__ bool isLast;
    __threadfence();
    if (threadIdx.x == 0) {
        unsigned int prev = atomicAdd(&g_done, 1u);
        isLast = (prev == NPART - 1);
    }
    __syncthreads();
    if (!isLast) return;

    float d = 0.0f, a = 0.0f, b = 0.0f;
    int c = 0, e = 0;
    #pragma unroll
    for (int i = 0; i < NPART / TPB; ++i) {
        int idx = threadIdx.x + i * TPB;
        d += g_pd[idx]; a += g_po[idx]; b += g_pv[idx];
        c += g_oc[idx]; e += g_vc[idx];
    }
    d = warp_red_f(d); a = warp_red_f(a); b = warp_red_f(b);
    c = warp_red_i(c); e = warp_red_i(e);
    if (lane == 0) {
        sd[warp] = d; so[warp] = a; sv[warp] = b; soc[warp] = c; svc[warp] = e;
    }
    __syncthreads();
    if (warp == 0) {
        d = (lane < WPB) ? sd[lane] : 0.0f;
        a = (lane < WPB) ? so[lane] : 0.0f;
        b = (lane < WPB) ? sv[lane] : 0.0f;
        c = (lane < WPB) ? soc[lane] : 0;
        e = (lane < WPB) ? svc[lane] : 0;
        d = warp_red_f(d); a = warp_red_f(a); b = warp_red_f(b);
        c = warp_red_i(c); e = warp_red_i(e);
        if (lane == 0) {
            double loss = (double)d / ((double)NN * VV * HH);   // DIST_COST=1
            if (c > 0) loss += ((double)a / (double)c) * 0.1;   // OBST_COST
            if (e > 0) loss += ((double)b / (double)e) * 0.1;   // VEH_COST
            out[0] = (float)loss;
            g_done = 0;   // reset for next graph replay
        }
    }
}

extern "C" void kernel_launch(void* const* d_in, const int* in_sizes, int n_in,
                              void* d_out, int out_size) {
    const float* pred   = (const float*)d_in[0];   // (N, V, H, 1) f32
    const float* inputs = (const float*)d_in[1];   // (N, 80) f32
    float* out = (float*)d_out;

    loss_kernel<<<NPART, TPB>>>(pred, inputs, out);
}